// round 1
// baseline (speedup 1.0000x reference)
#include <cuda_runtime.h>
#include <cstdint>

// Problem constants
#define B_  16
#define C_  256
#define H_  32
#define W_  32
#define N_  256
#define HW_ 1024

// Scratch (device globals; no allocation allowed)
__device__ float g_W[C_ * 9 * N_];   // [c][s][n], pre-scaled by 1/9
__device__ float g_biasf[N_];        // mean_s bias[s][n]

// ---------------------------------------------------------------------------
// Kernel 1: build combined butterfly matrices M_s = B2_s * B1_s per tap s.
// Each block: one s (9) x one 32-column chunk (8). Applies the 16 butterfly
// stages to identity columns held in shared memory (pitch 33 -> conflict-free).
// ---------------------------------------------------------------------------
__global__ void bfly_build_kernel(const float* __restrict__ tw1,
                                  const float* __restrict__ tw2) {
    __shared__ float M[256 * 33];
    const int s     = blockIdx.x;   // 0..8
    const int chunk = blockIdx.y;   // 0..7
    const int tid   = threadIdx.x;  // 256 threads

    // identity columns c = chunk*32 + col
    for (int idx = tid; idx < 256 * 32; idx += 256) {
        int n = idx >> 5, col = idx & 31;
        M[n * 33 + col] = (n == chunk * 32 + col) ? 1.0f : 0.0f;
    }

    auto stage = [&](const float* __restrict__ tw, int sh) {
        __syncthreads();
        const int st = 1 << sh;
        for (int task = tid; task < 128 * 32; task += 256) {
            int pr  = task >> 5, col = task & 31;
            int l   = pr & (st - 1);
            int k0  = ((pr >> sh) << (sh + 1)) | l;
            int k1  = k0 + st;
            // twiddle[s, st-1+l, i, k] as float4 {t00,t01,t10,t11}
            const float4 t = *(const float4*)(tw + ((size_t)s * 255 + (st - 1) + l) * 4);
            float a = M[k0 * 33 + col];
            float b = M[k1 * 33 + col];
            M[k0 * 33 + col] = t.x * a + t.y * b;
            M[k1 * 33 + col] = t.z * a + t.w * b;
        }
    };

    // increasing=False: strides 128..1 with twiddle1, then increasing=True: 1..128 with twiddle2
    for (int sh = 7; sh >= 0; --sh) stage(tw1, sh);
    for (int sh = 0; sh <= 7; ++sh) stage(tw2, sh);

    __syncthreads();
    const float inv9 = 1.0f / 9.0f;
    for (int idx = tid; idx < 256 * 32; idx += 256) {
        int n = idx & 255, col = idx >> 8;            // n fastest -> coalesced gmem write
        int c = chunk * 32 + col;
        g_W[((size_t)c * 9 + s) * 256 + n] = M[n * 33 + col] * inv9;
    }
}

__global__ void bias_fold_kernel(const float* __restrict__ bias) {
    int n = threadIdx.x;
    float acc = 0.f;
    #pragma unroll
    for (int s = 0; s < 9; ++s) acc += bias[s * 256 + n];
    g_biasf[n] = acc * (1.0f / 9.0f);
}

// ---------------------------------------------------------------------------
// Packed f32x2 helpers (sm_103a packed fp32 FMA pipe, 2x FFMA throughput)
// ---------------------------------------------------------------------------
typedef unsigned long long u64_t;
__device__ __forceinline__ u64_t pack2(float lo, float hi) {
    u64_t r; asm("mov.b64 %0, {%1, %2};" : "=l"(r) : "f"(lo), "f"(hi)); return r;
}
__device__ __forceinline__ void fma2(u64_t& d, u64_t a, u64_t b) {
    asm("fma.rn.f32x2 %0, %1, %2, %0;" : "+l"(d) : "l"(a), "l"(b));
}
__device__ __forceinline__ float2 unpack2(u64_t v) {
    float2 f; asm("mov.b64 {%0, %1}, %2;" : "=f"(f.x), "=f"(f.y) : "l"(v)); return f;
}

// ---------------------------------------------------------------------------
// Kernel 2: direct 3x3 conv, C=256 -> N=256, pad 1.
// Block: (b, y-pair, 64-n tile). 256 threads = 2y x 8xg(4x) x 16ng(4n).
// Per thread: 4x * 4n accumulators as 8 packed f32x2.
// Channels processed in chunks of 8 staged through shared memory.
// ---------------------------------------------------------------------------
#define NT  64
#define CCH 8

__global__ void __launch_bounds__(256)
conv_kernel(const float* __restrict__ x, float* __restrict__ out) {
    __shared__ float ish[CCH][4][36];     // input rows y0-1..y0+2, x -1..32 at +1 offset
    __shared__ float wsh[CCH][9][NT];     // weights [cc][tap][n]

    const int tid = threadIdx.x;
    const int ng  = tid & 15;             // 16 groups of 4 n
    const int xg  = (tid >> 4) & 7;       // 8 groups of 4 x
    const int ty  = tid >> 7;             // 0..1

    const int n0 = blockIdx.x * NT;
    const int y0 = blockIdx.y * 2;
    const int b  = blockIdx.z;

    u64_t acc[4][2];
    #pragma unroll
    for (int i = 0; i < 4; ++i) { acc[i][0] = 0ull; acc[i][1] = 0ull; }

    const float* xb = x + (size_t)b * C_ * HW_;

    for (int c0 = 0; c0 < C_; c0 += CCH) {
        __syncthreads();
        // stage inputs: CCH*4*34 = 1088 elems (zero-padded halo)
        for (int idx = tid; idx < CCH * 4 * 34; idx += 256) {
            int cc  = idx / 136;
            int rem = idx - cc * 136;
            int r   = rem / 34;
            int xx  = rem - r * 34;       // 0..33
            int gy  = y0 - 1 + r;
            int gx  = xx - 1;
            float v = 0.f;
            if ((unsigned)gy < 32u && (unsigned)gx < 32u)
                v = xb[(size_t)(c0 + cc) * HW_ + gy * 32 + gx];
            ish[cc][r][xx] = v;
        }
        // stage weights: CCH*9*NT/4 = 1152 float4
        for (int idx = tid; idx < CCH * 9 * (NT / 4); idx += 256) {
            int row = idx >> 4;           // cc*9 + s  (0..71)
            int v4  = idx & 15;
            int cc  = row / 9;
            int s   = row - cc * 9;
            float4 w = *(const float4*)(g_W + ((size_t)(c0 + cc) * 9 + s) * 256 + n0 + v4 * 4);
            *(float4*)&wsh[cc][s][v4 * 4] = w;
        }
        __syncthreads();

        #pragma unroll
        for (int cc = 0; cc < CCH; ++cc) {
            #pragma unroll
            for (int dy = 0; dy < 3; ++dy) {
                const float* ir = &ish[cc][ty + dy][xg * 4]; // covers i+dx in 0..5
                u64_t pv[6];
                #pragma unroll
                for (int j = 0; j < 6; ++j) { float v = ir[j]; pv[j] = pack2(v, v); }
                #pragma unroll
                for (int dx = 0; dx < 3; ++dx) {
                    const float4 w = *(const float4*)&wsh[cc][dy * 3 + dx][ng * 4];
                    u64_t wlo = pack2(w.x, w.y);
                    u64_t whi = pack2(w.z, w.w);
                    #pragma unroll
                    for (int i = 0; i < 4; ++i) {
                        fma2(acc[i][0], pv[dx + i], wlo);
                        fma2(acc[i][1], pv[dx + i], whi);
                    }
                }
            }
        }
    }

    // epilogue: add folded bias, write out[b][n][y][x]
    const int y  = y0 + ty;
    const int nb = n0 + ng * 4;
    float bf[4];
    #pragma unroll
    for (int j = 0; j < 4; ++j) bf[j] = g_biasf[nb + j];
    #pragma unroll
    for (int i = 0; i < 4; ++i) {
        int xo = xg * 4 + i;
        float2 lo = unpack2(acc[i][0]);
        float2 hi = unpack2(acc[i][1]);
        float* op = out + (((size_t)b * N_ + nb) * 32 + y) * 32 + xo;
        op[0]        = lo.x + bf[0];
        op[HW_]      = lo.y + bf[1];
        op[2 * HW_]  = hi.x + bf[2];
        op[3 * HW_]  = hi.y + bf[3];
    }
}

// ---------------------------------------------------------------------------
extern "C" void kernel_launch(void* const* d_in, const int* in_sizes, int n_in,
                              void* d_out, int out_size) {
    const float* x    = (const float*)d_in[0];   // (16,256,32,32)
    const float* tw1  = (const float*)d_in[1];   // (9,255,2,2)
    const float* tw2  = (const float*)d_in[2];   // (9,255,2,2)
    const float* bias = (const float*)d_in[3];   // (9,256)
    float* out = (float*)d_out;                  // (16,256,32,32)

    bfly_build_kernel<<<dim3(9, 8), 256>>>(tw1, tw2);
    bias_fold_kernel<<<1, 256>>>(bias);
    conv_kernel<<<dim3(N_ / NT, H_ / 2, B_), 256>>>(x, out);
}

// round 4
// speedup vs baseline: 2.0502x; 2.0502x over previous
#include <cuda_runtime.h>
#include <cuda_bf16.h>
#include <cstdint>

// ---------------------------------------------------------------------------
// out = mean_s( B2_s B1_s patch_s + bias_s )  ==  3x3 conv 256->256, pad 1.
// Collapsed to GEMM D[m,n] = sum_k A[m,k]*B[n,k], m = b*h*w (16384), n = 256,
// k = tap*256 + c (2304), bf16 2-term split -> 3 passes (hh, hl, lh) = 108
// K-chunks of 64. Mainloop: warp mma.sync (HMMA) + ldmatrix + cp.async
// (tcgen05 is ptxas-gated off: harness targets sm_103, not sm_103a).
// ---------------------------------------------------------------------------

#define B_   16
#define C_   256
#define N_   256
#define HW_  1024
#define KTOT 2304
#define PAD_ 34
#define NCH  108

// ------------------------- device scratch (no alloc) -----------------------
__device__ __align__(16) __nv_bfloat16 g_Bh[N_ * KTOT];             // W hi [n][tap*256+c]
__device__ __align__(16) __nv_bfloat16 g_Bl[N_ * KTOT];             // W lo
__device__ __align__(16) __nv_bfloat16 g_Ah[B_ * PAD_ * PAD_ * C_]; // x hi [b][py][px][c]
__device__ __align__(16) __nv_bfloat16 g_Al[B_ * PAD_ * PAD_ * C_]; // x lo
__device__ float g_biasf[N_];

// ------------------------------ PTX helpers --------------------------------
__device__ __forceinline__ uint32_t smem_u32(const void* p) {
    uint32_t a;
    asm("{ .reg .u64 t; cvta.to.shared.u64 t, %1; cvt.u32.u64 %0, t; }"
        : "=r"(a) : "l"(p));
    return a;
}
#define SW128(o) ((o) ^ ((((uint32_t)(o)) >> 3) & 0x70))

#define CP_ASYNC16(dst, src) \
    asm volatile("cp.async.cg.shared.global [%0], [%1], 16;" \
                 :: "r"(dst), "l"(src) : "memory")
#define CP_COMMIT() asm volatile("cp.async.commit_group;" ::: "memory")
#define CP_WAIT(n)  asm volatile("cp.async.wait_group %0;" :: "n"(n) : "memory")

__device__ __forceinline__ void ldmx4(uint32_t* r, uint32_t addr) {
    asm volatile("ldmatrix.sync.aligned.m8n8.x4.shared.b16 {%0,%1,%2,%3}, [%4];"
                 : "=r"(r[0]), "=r"(r[1]), "=r"(r[2]), "=r"(r[3]) : "r"(addr));
}
__device__ __forceinline__ void mma16816(float* d, const uint32_t* a,
                                         uint32_t b0, uint32_t b1) {
    asm volatile(
        "mma.sync.aligned.m16n8k16.row.col.f32.bf16.bf16.f32 "
        "{%0,%1,%2,%3}, {%4,%5,%6,%7}, {%8,%9}, {%0,%1,%2,%3};"
        : "+f"(d[0]), "+f"(d[1]), "+f"(d[2]), "+f"(d[3])
        : "r"(a[0]), "r"(a[1]), "r"(a[2]), "r"(a[3]), "r"(b0), "r"(b1));
}

// ---------------------------------------------------------------------------
// Kernel 1: build combined butterfly matrices M_s = B2_s * B1_s, split bf16.
// ---------------------------------------------------------------------------
__global__ void bfly_build_kernel(const float* __restrict__ tw1,
                                  const float* __restrict__ tw2) {
    __shared__ float M[256 * 17];
    const int s     = blockIdx.x;   // tap
    const int chunk = blockIdx.y;   // 16 columns each
    const int tid   = threadIdx.x;

    for (int idx = tid; idx < 256 * 16; idx += 256) {
        int n = idx >> 4, col = idx & 15;
        M[n * 17 + col] = (n == chunk * 16 + col) ? 1.0f : 0.0f;
    }

    auto stage = [&](const float* __restrict__ tw, int sh) {
        __syncthreads();
        const int st = 1 << sh;
        for (int task = tid; task < 128 * 16; task += 256) {
            int pr  = task >> 4, col = task & 15;
            int l   = pr & (st - 1);
            int k0  = ((pr >> sh) << (sh + 1)) | l;
            int k1  = k0 + st;
            const float4 t = *(const float4*)(tw + ((size_t)s * 255 + (st - 1) + l) * 4);
            float a = M[k0 * 17 + col];
            float b = M[k1 * 17 + col];
            M[k0 * 17 + col] = t.x * a + t.y * b;
            M[k1 * 17 + col] = t.z * a + t.w * b;
        }
    };

    for (int sh = 7; sh >= 0; --sh) stage(tw1, sh);   // increasing=False (tw1)
    for (int sh = 0; sh <= 7; ++sh) stage(tw2, sh);   // increasing=True  (tw2)

    __syncthreads();
    const float inv9 = 1.0f / 9.0f;
    for (int idx = tid; idx < 256 * 16; idx += 256) {
        int col = idx & 15, n = idx >> 4;
        int c = chunk * 16 + col;
        float w = M[n * 17 + col] * inv9;
        __nv_bfloat16 hi = __float2bfloat16(w);
        __nv_bfloat16 lo = __float2bfloat16(w - __bfloat162float(hi));
        size_t o = (size_t)n * KTOT + s * 256 + c;
        g_Bh[o] = hi;
        g_Bl[o] = lo;
    }
}

__global__ void bias_fold_kernel(const float* __restrict__ bias) {
    int n = threadIdx.x;
    float acc = 0.f;
    #pragma unroll
    for (int s = 0; s < 9; ++s) acc += bias[s * 256 + n];
    g_biasf[n] = acc * (1.0f / 9.0f);
}

// ---------------------------------------------------------------------------
// Kernel 2: zero padded input buffers.
// ---------------------------------------------------------------------------
__global__ void zero_pad_kernel() {
    const uint32_t n4 = (B_ * PAD_ * PAD_ * C_) / 8;
    uint32_t i = blockIdx.x * blockDim.x + threadIdx.x;
    uint4 z = make_uint4(0, 0, 0, 0);
    if (i < n4) {
        ((uint4*)g_Ah)[i] = z;
        ((uint4*)g_Al)[i] = z;
    }
}

// ---------------------------------------------------------------------------
// Kernel 3: transpose + bf16 split: x[b][c][y][x] -> Ap[b][y+1][x+1][c]
// ---------------------------------------------------------------------------
__global__ void split_pad_kernel(const float* __restrict__ x) {
    __shared__ float sm[256 * 33];
    const int t  = threadIdx.x;
    const int b  = blockIdx.x >> 5;
    const int y  = blockIdx.x & 31;
    const int w  = t >> 5, xc = t & 31;

    #pragma unroll 4
    for (int i = 0; i < 32; ++i) {
        int c = i * 8 + w;
        sm[c * 33 + xc] = x[(((size_t)b * 256 + c) * 32 + y) * 32 + xc];
    }
    __syncthreads();

    #pragma unroll 4
    for (int xi = 0; xi < 32; ++xi) {
        float v = sm[t * 33 + xi];
        __nv_bfloat16 hi = __float2bfloat16(v);
        __nv_bfloat16 lo = __float2bfloat16(v - __bfloat162float(hi));
        size_t dst = (((size_t)b * PAD_ + y + 1) * PAD_ + xi + 1) * 256 + t;
        g_Ah[dst] = hi;
        g_Al[dst] = lo;
    }
}

// ---------------------------------------------------------------------------
// Kernel 4: HMMA GEMM. CTA tile 128M x 128N, 8 warps (4M x 2N), each warp
// 32x64 via m16n8k16. 2-stage cp.async ring, K-chunk 64 bf16.
// smem stage: A 128x128B (16KB) + B 128x128B (16KB), SW128 swizzle.
// ---------------------------------------------------------------------------
#define A_ST 16384
#define B_OF 32768
#define SMEM_TOT 65536

__device__ __forceinline__ void load_chunk(uint32_t sb, int j, int ch,
                                           int b, int y0, int n0, int tid) {
    const int term = ch / 36;              // 0:hh 1:hl 2:lh
    const int r    = ch - term * 36;
    const int tap  = r >> 2;
    const int cc   = r & 3;
    const int dy   = tap / 3, dx = tap - dy * 3;
    const int cbase = cc * 64;

    const __nv_bfloat16* Asrc = (term < 2) ? g_Ah : g_Al;
    const __nv_bfloat16* Bsrc = (term == 1) ? g_Bl : g_Bh;

    const int arow  = tid >> 1;            // 0..127
    const int ahalf = tid & 1;             // 64B half
    const uint32_t ro = (uint32_t)arow * 128 + ahalf * 64;

    // A tile: row r <-> (yy = r>>5, x = r&31)
    const int py = y0 + (arow >> 5) + dy;
    const int px = (arow & 31) + dx;
    const char* asrc = (const char*)(Asrc +
        (((size_t)b * PAD_ + py) * PAD_ + px) * 256 + cbase) + ahalf * 64;
    const uint32_t abase = sb + (uint32_t)j * A_ST;
    #pragma unroll
    for (int q = 0; q < 4; ++q)
        CP_ASYNC16(abase + SW128(ro + q * 16), asrc + q * 16);

    // B tile: row -> n0 + row
    const char* bsrc = (const char*)(Bsrc +
        (size_t)(n0 + arow) * KTOT + tap * 256 + cbase) + ahalf * 64;
    const uint32_t bbase = sb + B_OF + (uint32_t)j * A_ST;
    #pragma unroll
    for (int q = 0; q < 4; ++q)
        CP_ASYNC16(bbase + SW128(ro + q * 16), bsrc + q * 16);
}

__global__ void __launch_bounds__(256, 2)
gemm_kernel(float* __restrict__ out) {
    extern __shared__ char smem[];
    const uint32_t sb = smem_u32(smem);
    const int tid  = threadIdx.x;
    const int lane = tid & 31;
    const int wid  = tid >> 5;
    const int wm   = wid & 3;              // M-warp (32 rows)
    const int wn   = wid >> 2;             // N-warp (64 cols)

    const int blk = blockIdx.x;            // 128 M-tiles
    const int b   = blk >> 3;
    const int y0  = (blk & 7) * 4;
    const int n0  = blockIdx.y * 128;

    float acc[2][8][4];
    #pragma unroll
    for (int mi = 0; mi < 2; ++mi)
        #pragma unroll
        for (int ni = 0; ni < 8; ++ni)
            #pragma unroll
            for (int v = 0; v < 4; ++v) acc[mi][ni][v] = 0.f;

    // ldmatrix address components (constant across chunks)
    const uint32_t lrow = lane & 15;
    const uint32_t lcol = (lane >> 4) * 16;

    load_chunk(sb, 0, 0, b, y0, n0, tid);
    CP_COMMIT();

    for (int ch = 0; ch < NCH; ++ch) {
        if (ch + 1 < NCH) {
            load_chunk(sb, (ch + 1) & 1, ch + 1, b, y0, n0, tid);
            CP_COMMIT();
            CP_WAIT(1);
        } else {
            CP_WAIT(0);
        }
        __syncthreads();

        const uint32_t abase = sb + (uint32_t)(ch & 1) * A_ST;
        const uint32_t bbase = sb + B_OF + (uint32_t)(ch & 1) * A_ST;

        #pragma unroll
        for (int ks = 0; ks < 4; ++ks) {
            uint32_t afr[2][4];
            #pragma unroll
            for (int mi = 0; mi < 2; ++mi) {
                uint32_t row = wm * 32 + mi * 16 + lrow;
                ldmx4(afr[mi], abase + SW128(row * 128 + ks * 32 + lcol));
            }
            uint32_t bfr[4][4];
            #pragma unroll
            for (int nq = 0; nq < 4; ++nq) {
                uint32_t row = wn * 64 + nq * 16 + lrow;
                ldmx4(bfr[nq], bbase + SW128(row * 128 + ks * 32 + lcol));
            }
            #pragma unroll
            for (int mi = 0; mi < 2; ++mi)
                #pragma unroll
                for (int ni = 0; ni < 8; ++ni)
                    mma16816(acc[mi][ni], afr[mi],
                             bfr[ni >> 1][ni & 1], bfr[ni >> 1][(ni & 1) + 2]);
        }
        __syncthreads();
    }

    // epilogue: bias + store. lane l: rows rbase+{0,8}, cols n+{0,1}.
    float bias2[8][2];
    #pragma unroll
    for (int ni = 0; ni < 8; ++ni) {
        int n = n0 + wn * 64 + ni * 8 + (lane & 3) * 2;
        bias2[ni][0] = g_biasf[n];
        bias2[ni][1] = g_biasf[n + 1];
    }
    #pragma unroll
    for (int mi = 0; mi < 2; ++mi) {
        const int rbase = wm * 32 + mi * 16 + (lane >> 2);
        #pragma unroll
        for (int ni = 0; ni < 8; ++ni) {
            const int n = n0 + wn * 64 + ni * 8 + (lane & 3) * 2;
            #pragma unroll
            for (int hrow = 0; hrow < 2; ++hrow) {
                const int row = rbase + hrow * 8;
                const int yy = row >> 5, xx = row & 31;
                float* op = out + (((size_t)b * N_ + n) * 32 + y0 + yy) * 32 + xx;
                op[0]   = acc[mi][ni][2 * hrow]     + bias2[ni][0];
                op[HW_] = acc[mi][ni][2 * hrow + 1] + bias2[ni][1];
            }
        }
    }
}

// ---------------------------------------------------------------------------
extern "C" void kernel_launch(void* const* d_in, const int* in_sizes, int n_in,
                              void* d_out, int out_size) {
    const float* x    = (const float*)d_in[0];   // (16,256,32,32)
    const float* tw1  = (const float*)d_in[1];   // (9,255,2,2)
    const float* tw2  = (const float*)d_in[2];   // (9,255,2,2)
    const float* bias = (const float*)d_in[3];   // (9,256)
    float* out = (float*)d_out;                  // (16,256,32,32)

    cudaFuncSetAttribute(gemm_kernel,
                         cudaFuncAttributeMaxDynamicSharedMemorySize, SMEM_TOT);

    zero_pad_kernel<<<(B_ * PAD_ * PAD_ * C_ / 8 + 255) / 256, 256>>>();
    split_pad_kernel<<<B_ * 32, 256>>>(x);
    bfly_build_kernel<<<dim3(9, 16), 256>>>(tw1, tw2);
    bias_fold_kernel<<<1, 256>>>(bias);
    gemm_kernel<<<dim3(128, 2), 256, SMEM_TOT>>>(out);
}

// round 7
// speedup vs baseline: 2.1146x; 1.0315x over previous
#include <cuda_runtime.h>
#include <cuda_bf16.h>
#include <cstdint>

// ---------------------------------------------------------------------------
// out = mean_s( B2_s B1_s patch_s + bias_s )  ==  3x3 conv 256->256, pad 1.
// Collapsed GEMM D[m,n] = sum_k A[m,k]*B[n,k], m=16384, n=256, k=2304,
// bf16 2-term split -> 3 passes = 108 K-chunks of 64.
// R5: K-split 4 for SM load balance (grid 1024), partial buffers + fused
// reduce (deterministic), 3-stage cp.async ring, border-only zero.
// ---------------------------------------------------------------------------

#define B_   16
#define C_   256
#define N_   256
#define HW_  1024
#define KTOT 2304
#define PAD_ 34
#define NCH  108
#define KSPL 4
#define CPU_ (NCH / KSPL)        // 27 chunks per unit
#define OUTSZ (B_ * N_ * HW_)    // 4194304

// ------------------------- device scratch (no alloc) -----------------------
__device__ __align__(16) __nv_bfloat16 g_Bh[N_ * KTOT];
__device__ __align__(16) __nv_bfloat16 g_Bl[N_ * KTOT];
__device__ __align__(16) __nv_bfloat16 g_Ah[B_ * PAD_ * PAD_ * C_];
__device__ __align__(16) __nv_bfloat16 g_Al[B_ * PAD_ * PAD_ * C_];
__device__ __align__(16) float g_part[KSPL * OUTSZ];   // 67 MB partials
__device__ float g_biasf[N_];

// ------------------------------ PTX helpers --------------------------------
__device__ __forceinline__ uint32_t smem_u32(const void* p) {
    uint32_t a;
    asm("{ .reg .u64 t; cvta.to.shared.u64 t, %1; cvt.u32.u64 %0, t; }"
        : "=r"(a) : "l"(p));
    return a;
}
#define SW128(o) ((o) ^ ((((uint32_t)(o)) >> 3) & 0x70))

#define CP_ASYNC16(dst, src) \
    asm volatile("cp.async.cg.shared.global [%0], [%1], 16;" \
                 :: "r"(dst), "l"(src) : "memory")
#define CP_COMMIT() asm volatile("cp.async.commit_group;" ::: "memory")
#define CP_WAIT(n)  asm volatile("cp.async.wait_group %0;" :: "n"(n) : "memory")

__device__ __forceinline__ void ldmx4(uint32_t* r, uint32_t addr) {
    asm volatile("ldmatrix.sync.aligned.m8n8.x4.shared.b16 {%0,%1,%2,%3}, [%4];"
                 : "=r"(r[0]), "=r"(r[1]), "=r"(r[2]), "=r"(r[3]) : "r"(addr));
}
__device__ __forceinline__ void mma16816(float* d, const uint32_t* a,
                                         uint32_t b0, uint32_t b1) {
    asm volatile(
        "mma.sync.aligned.m16n8k16.row.col.f32.bf16.bf16.f32 "
        "{%0,%1,%2,%3}, {%4,%5,%6,%7}, {%8,%9}, {%0,%1,%2,%3};"
        : "+f"(d[0]), "+f"(d[1]), "+f"(d[2]), "+f"(d[3])
        : "r"(a[0]), "r"(a[1]), "r"(a[2]), "r"(a[3]), "r"(b0), "r"(b1));
}

// ---------------------------------------------------------------------------
// Kernel 1: combined butterfly matrices M_s = B2_s * B1_s, split bf16 hi/lo.
// ---------------------------------------------------------------------------
__global__ void bfly_build_kernel(const float* __restrict__ tw1,
                                  const float* __restrict__ tw2) {
    __shared__ float M[256 * 17];
    const int s     = blockIdx.x;
    const int chunk = blockIdx.y;
    const int tid   = threadIdx.x;

    for (int idx = tid; idx < 256 * 16; idx += 256) {
        int n = idx >> 4, col = idx & 15;
        M[n * 17 + col] = (n == chunk * 16 + col) ? 1.0f : 0.0f;
    }

    auto stage = [&](const float* __restrict__ tw, int sh) {
        __syncthreads();
        const int st = 1 << sh;
        for (int task = tid; task < 128 * 16; task += 256) {
            int pr  = task >> 4, col = task & 15;
            int l   = pr & (st - 1);
            int k0  = ((pr >> sh) << (sh + 1)) | l;
            int k1  = k0 + st;
            const float4 t = *(const float4*)(tw + ((size_t)s * 255 + (st - 1) + l) * 4);
            float a = M[k0 * 17 + col];
            float b = M[k1 * 17 + col];
            M[k0 * 17 + col] = t.x * a + t.y * b;
            M[k1 * 17 + col] = t.z * a + t.w * b;
        }
    };

    for (int sh = 7; sh >= 0; --sh) stage(tw1, sh);
    for (int sh = 0; sh <= 7; ++sh) stage(tw2, sh);

    __syncthreads();
    const float inv9 = 1.0f / 9.0f;
    for (int idx = tid; idx < 256 * 16; idx += 256) {
        int col = idx & 15, n = idx >> 4;
        int c = chunk * 16 + col;
        float w = M[n * 17 + col] * inv9;
        __nv_bfloat16 hi = __float2bfloat16(w);
        __nv_bfloat16 lo = __float2bfloat16(w - __bfloat162float(hi));
        size_t o = (size_t)n * KTOT + s * 256 + c;
        g_Bh[o] = hi;
        g_Bl[o] = lo;
    }
}

__global__ void bias_fold_kernel(const float* __restrict__ bias) {
    int n = threadIdx.x;
    float acc = 0.f;
    #pragma unroll
    for (int s = 0; s < 9; ++s) acc += bias[s * 256 + n];
    g_biasf[n] = acc * (1.0f / 9.0f);
}

// ---------------------------------------------------------------------------
// Kernel 2: zero only the pad borders (interior overwritten by split_pad).
// 16 b x 132 border cells x 32 uint4 (256 ch) = 67584 vec-stores per array.
// ---------------------------------------------------------------------------
__global__ void border_zero_kernel() {
    int idx = blockIdx.x * 256 + threadIdx.x;
    if (idx >= 16 * 132 * 32) return;
    int vec  = idx & 31;
    int cell = (idx >> 5) % 132;
    int b    = idx / (132 * 32);
    int py, px;
    if (cell < 34)      { py = 0;  px = cell; }
    else if (cell < 68) { py = 33; px = cell - 34; }
    else { int r = cell - 68; py = 1 + (r >> 1); px = (r & 1) * 33; }
    size_t base = (((size_t)b * PAD_ + py) * PAD_ + px) * 256;
    uint4 z = make_uint4(0, 0, 0, 0);
    ((uint4*)(g_Ah + base))[vec] = z;
    ((uint4*)(g_Al + base))[vec] = z;
}

// ---------------------------------------------------------------------------
// Kernel 3: transpose + bf16 split: x[b][c][y][x] -> Ap[b][y+1][x+1][c]
// ---------------------------------------------------------------------------
__global__ void split_pad_kernel(const float* __restrict__ x) {
    __shared__ float sm[256 * 33];
    const int t  = threadIdx.x;
    const int b  = blockIdx.x >> 5;
    const int y  = blockIdx.x & 31;
    const int w  = t >> 5, xc = t & 31;

    #pragma unroll 4
    for (int i = 0; i < 32; ++i) {
        int c = i * 8 + w;
        sm[c * 33 + xc] = x[(((size_t)b * 256 + c) * 32 + y) * 32 + xc];
    }
    __syncthreads();

    #pragma unroll 4
    for (int xi = 0; xi < 32; ++xi) {
        float v = sm[t * 33 + xi];
        __nv_bfloat16 hi = __float2bfloat16(v);
        __nv_bfloat16 lo = __float2bfloat16(v - __bfloat162float(hi));
        size_t dst = (((size_t)b * PAD_ + y + 1) * PAD_ + xi + 1) * 256 + t;
        g_Ah[dst] = hi;
        g_Al[dst] = lo;
    }
}

// ---------------------------------------------------------------------------
// Kernel 4: HMMA GEMM unit. CTA = 128M x 128N x 27-chunk K-slice.
// grid (128 m-tiles, 2 n-tiles, 4 k-splits) = 1024 CTAs -> ~6.9/SM balanced.
// 8 warps (4M x 2N), warp 32x64 via m16n8k16. 3-stage cp.async ring.
// ---------------------------------------------------------------------------
#define A_ST 16384
#define B_OF 49152                   // 3 A stages
#define SMEM_TOT 98304               // 3 x (16K A + 16K B)

__device__ __forceinline__ void load_chunk(uint32_t sb, int j, int gch,
                                           int b, int y0, int n0, int tid) {
    const int term = gch / 36;              // 0:hh 1:hl 2:lh
    const int r    = gch - term * 36;
    const int tap  = r >> 2;
    const int cc   = r & 3;
    const int dy   = tap / 3, dx = tap - dy * 3;
    const int cbase = cc * 64;

    const __nv_bfloat16* Asrc = (term < 2) ? g_Ah : g_Al;
    const __nv_bfloat16* Bsrc = (term == 1) ? g_Bl : g_Bh;

    const int arow  = tid >> 1;
    const int ahalf = tid & 1;
    const uint32_t ro = (uint32_t)arow * 128 + ahalf * 64;

    const int py = y0 + (arow >> 5) + dy;
    const int px = (arow & 31) + dx;
    const char* asrc = (const char*)(Asrc +
        (((size_t)b * PAD_ + py) * PAD_ + px) * 256 + cbase) + ahalf * 64;
    const uint32_t abase = sb + (uint32_t)j * A_ST;
    #pragma unroll
    for (int q = 0; q < 4; ++q)
        CP_ASYNC16(abase + SW128(ro + q * 16), asrc + q * 16);

    const char* bsrc = (const char*)(Bsrc +
        (size_t)(n0 + arow) * KTOT + tap * 256 + cbase) + ahalf * 64;
    const uint32_t bbase = sb + B_OF + (uint32_t)j * A_ST;
    #pragma unroll
    for (int q = 0; q < 4; ++q)
        CP_ASYNC16(bbase + SW128(ro + q * 16), bsrc + q * 16);
}

__global__ void __launch_bounds__(256, 2)
gemm_kernel() {
    extern __shared__ char smem[];
    const uint32_t sb = smem_u32(smem);
    const int tid  = threadIdx.x;
    const int lane = tid & 31;
    const int wid  = tid >> 5;
    const int wm   = wid & 3;
    const int wn   = wid >> 2;

    const int blk = blockIdx.x;
    const int b   = blk >> 3;
    const int y0  = (blk & 7) * 4;
    const int n0  = blockIdx.y * 128;
    const int z   = blockIdx.z;            // k-split
    const int g0  = z * CPU_;

    float acc[2][8][4];
    #pragma unroll
    for (int mi = 0; mi < 2; ++mi)
        #pragma unroll
        for (int ni = 0; ni < 8; ++ni)
            #pragma unroll
            for (int v = 0; v < 4; ++v) acc[mi][ni][v] = 0.f;

    const uint32_t lrow = lane & 15;
    const uint32_t lcol = (lane >> 4) * 16;

    load_chunk(sb, 0, g0 + 0, b, y0, n0, tid);
    CP_COMMIT();
    load_chunk(sb, 1, g0 + 1, b, y0, n0, tid);
    CP_COMMIT();

    int stg = 0;
    for (int i = 0; i < CPU_; ++i) {
        if (i + 2 < CPU_) {
            int js = (i + 2) % 3;
            load_chunk(sb, js, g0 + i + 2, b, y0, n0, tid);
            CP_COMMIT();
            CP_WAIT(2);
        } else if (i + 1 < CPU_) {
            CP_WAIT(1);
        } else {
            CP_WAIT(0);
        }
        __syncthreads();

        const uint32_t abase = sb + (uint32_t)stg * A_ST;
        const uint32_t bbase = sb + B_OF + (uint32_t)stg * A_ST;

        #pragma unroll
        for (int ks = 0; ks < 4; ++ks) {
            uint32_t afr[2][4];
            #pragma unroll
            for (int mi = 0; mi < 2; ++mi) {
                uint32_t row = wm * 32 + mi * 16 + lrow;
                ldmx4(afr[mi], abase + SW128(row * 128 + ks * 32 + lcol));
            }
            uint32_t bfr[4][4];
            #pragma unroll
            for (int nq = 0; nq < 4; ++nq) {
                uint32_t row = wn * 64 + nq * 16 + lrow;
                ldmx4(bfr[nq], bbase + SW128(row * 128 + ks * 32 + lcol));
            }
            #pragma unroll
            for (int mi = 0; mi < 2; ++mi)
                #pragma unroll
                for (int ni = 0; ni < 8; ++ni)
                    mma16816(acc[mi][ni], afr[mi],
                             bfr[ni >> 1][ni & 1], bfr[ni >> 1][(ni & 1) + 2]);
        }
        __syncthreads();
        stg = (stg + 1) % 3;
    }

    // epilogue: store raw partials (bias folded in reduce kernel)
    float* part = g_part + (size_t)z * OUTSZ;
    #pragma unroll
    for (int mi = 0; mi < 2; ++mi) {
        const int rbase = wm * 32 + mi * 16 + (lane >> 2);
        #pragma unroll
        for (int ni = 0; ni < 8; ++ni) {
            const int n = n0 + wn * 64 + ni * 8 + (lane & 3) * 2;
            #pragma unroll
            for (int hrow = 0; hrow < 2; ++hrow) {
                const int row = rbase + hrow * 8;
                const int yy = row >> 5, xx = row & 31;
                float* op = part + (((size_t)b * N_ + n) * 32 + y0 + yy) * 32 + xx;
                op[0]   = acc[mi][ni][2 * hrow];
                op[HW_] = acc[mi][ni][2 * hrow + 1];
            }
        }
    }
}

// ---------------------------------------------------------------------------
// Kernel 5: reduce 4 partials + bias -> out. float4 vectorized.
// ---------------------------------------------------------------------------
__global__ void reduce_kernel(float* __restrict__ out) {
    const uint32_t i = blockIdx.x * 256 + threadIdx.x;   // float4 index
    const uint32_t nf4 = OUTSZ / 4;
    if (i >= nf4) return;
    const float4* p = (const float4*)g_part;
    float4 a = p[i];
    float4 b = p[i + nf4];
    float4 c = p[i + 2 * nf4];
    float4 d = p[i + 3 * nf4];
    float bn = g_biasf[(i >> 8) & 255];
    float4 o;
    o.x = a.x + b.x + c.x + d.x + bn;
    o.y = a.y + b.y + c.y + d.y + bn;
    o.z = a.z + b.z + c.z + d.z + bn;
    o.w = a.w + b.w + c.w + d.w + bn;
    ((float4*)out)[i] = o;
}

// ---------------------------------------------------------------------------
extern "C" void kernel_launch(void* const* d_in, const int* in_sizes, int n_in,
                              void* d_out, int out_size) {
    const float* x    = (const float*)d_in[0];
    const float* tw1  = (const float*)d_in[1];
    const float* tw2  = (const float*)d_in[2];
    const float* bias = (const float*)d_in[3];
    float* out = (float*)d_out;

    cudaFuncSetAttribute(gemm_kernel,
                         cudaFuncAttributeMaxDynamicSharedMemorySize, SMEM_TOT);

    border_zero_kernel<<<(16 * 132 * 32 + 255) / 256, 256>>>();
    split_pad_kernel<<<B_ * 32, 256>>>(x);
    bfly_build_kernel<<<dim3(9, 16), 256>>>(tw1, tw2);
    bias_fold_kernel<<<1, 256>>>(bias);
    gemm_kernel<<<dim3(128, 2, KSPL), 256, SMEM_TOT>>>();
    reduce_kernel<<<(OUTSZ / 4 + 255) / 256, 256>>>(out);
}

// round 12
// speedup vs baseline: 5.0000x; 2.3645x over previous
#include <cuda_runtime.h>
#include <cuda_fp16.h>
#include <cstdint>

// ---------------------------------------------------------------------------
// out = mean_s( B2_s B1_s patch_s + bias_s )  ==  3x3 conv 256->256, pad 1.
// Collapsed GEMM D[m,n] = sum_k A[m,k]*B[n,k], m=16384, n=256, k=2304.
// R8 (re-bench after infra failure): single-pass fp16 HMMA
// (precision model: rel_err ~2e-4 < 1e-3).
// 36 K-chunks of 64, 3-stage cp.async ring, direct epilogue (bias + x16).
// B stored pre-scaled by 1/(9*16) to guard fp16 overflow.
// ---------------------------------------------------------------------------

#define B_   16
#define C_   256
#define N_   256
#define HW_  1024
#define KTOT 2304
#define PAD_ 34
#define NCH  36

// ------------------------- device scratch (no alloc) -----------------------
__device__ __align__(16) __half g_Bh[N_ * KTOT];              // W [n][tap*256+c] * 1/144
__device__ __align__(16) __half g_Ah[B_ * PAD_ * PAD_ * C_];  // x [b][py][px][c] fp16

// ------------------------------ PTX helpers --------------------------------
__device__ __forceinline__ uint32_t smem_u32(const void* p) {
    uint32_t a;
    asm("{ .reg .u64 t; cvta.to.shared.u64 t, %1; cvt.u32.u64 %0, t; }"
        : "=r"(a) : "l"(p));
    return a;
}
#define SW128(o) ((o) ^ ((((uint32_t)(o)) >> 3) & 0x70))

#define CP_ASYNC16(dst, src) \
    asm volatile("cp.async.cg.shared.global [%0], [%1], 16;" \
                 :: "r"(dst), "l"(src) : "memory")
#define CP_COMMIT() asm volatile("cp.async.commit_group;" ::: "memory")
#define CP_WAIT(n)  asm volatile("cp.async.wait_group %0;" :: "n"(n) : "memory")

__device__ __forceinline__ void ldmx4(uint32_t* r, uint32_t addr) {
    asm volatile("ldmatrix.sync.aligned.m8n8.x4.shared.b16 {%0,%1,%2,%3}, [%4];"
                 : "=r"(r[0]), "=r"(r[1]), "=r"(r[2]), "=r"(r[3]) : "r"(addr));
}
__device__ __forceinline__ void mma16816(float* d, const uint32_t* a,
                                         uint32_t b0, uint32_t b1) {
    asm volatile(
        "mma.sync.aligned.m16n8k16.row.col.f32.f16.f16.f32 "
        "{%0,%1,%2,%3}, {%4,%5,%6,%7}, {%8,%9}, {%0,%1,%2,%3};"
        : "+f"(d[0]), "+f"(d[1]), "+f"(d[2]), "+f"(d[3])
        : "r"(a[0]), "r"(a[1]), "r"(a[2]), "r"(a[3]), "r"(b0), "r"(b1));
}

// ---------------------------------------------------------------------------
// Kernel 1: combined butterfly matrices M_s = B2_s * B1_s -> fp16 * 1/144.
// ---------------------------------------------------------------------------
__global__ void bfly_build_kernel(const float* __restrict__ tw1,
                                  const float* __restrict__ tw2) {
    __shared__ float M[256 * 17];
    const int s     = blockIdx.x;
    const int chunk = blockIdx.y;
    const int tid   = threadIdx.x;

    for (int idx = tid; idx < 256 * 16; idx += 256) {
        int n = idx >> 4, col = idx & 15;
        M[n * 17 + col] = (n == chunk * 16 + col) ? 1.0f : 0.0f;
    }

    auto stage = [&](const float* __restrict__ tw, int sh) {
        __syncthreads();
        const int st = 1 << sh;
        for (int task = tid; task < 128 * 16; task += 256) {
            int pr  = task >> 4, col = task & 15;
            int l   = pr & (st - 1);
            int k0  = ((pr >> sh) << (sh + 1)) | l;
            int k1  = k0 + st;
            const float4 t = *(const float4*)(tw + ((size_t)s * 255 + (st - 1) + l) * 4);
            float a = M[k0 * 17 + col];
            float b = M[k1 * 17 + col];
            M[k0 * 17 + col] = t.x * a + t.y * b;
            M[k1 * 17 + col] = t.z * a + t.w * b;
        }
    };

    for (int sh = 7; sh >= 0; --sh) stage(tw1, sh);   // increasing=False (tw1)
    for (int sh = 0; sh <= 7; ++sh) stage(tw2, sh);   // increasing=True  (tw2)

    __syncthreads();
    const float sc = 1.0f / (9.0f * 16.0f);
    for (int idx = tid; idx < 256 * 16; idx += 256) {
        int col = idx & 15, n = idx >> 4;
        int c = chunk * 16 + col;
        g_Bh[(size_t)n * KTOT + s * 256 + c] = __float2half(M[n * 17 + col] * sc);
    }
}

// ---------------------------------------------------------------------------
// Kernel 2: transpose + fp16: x[b][c][y][x] -> A[b][y+1][x+1][c]; also zero
// the pad border (disjoint addresses, handled by leading thread indices).
// ---------------------------------------------------------------------------
__global__ void split_pad_kernel(const float* __restrict__ x) {
    __shared__ float sm[256 * 33];
    const int t  = threadIdx.x;
    const int b  = blockIdx.x >> 5;
    const int y  = blockIdx.x & 31;

    // border zero: 16 b * 132 cells * 32 uint4 (512B = 256 fp16) = 67584 tasks
    {
        int idx = blockIdx.x * 256 + t;
        if (idx < 16 * 132 * 32) {
            int vec  = idx & 31;
            int cell = (idx >> 5) % 132;
            int bb   = idx / (132 * 32);
            int py, px;
            if (cell < 34)      { py = 0;  px = cell; }
            else if (cell < 68) { py = 33; px = cell - 34; }
            else { int r = cell - 68; py = 1 + (r >> 1); px = (r & 1) * 33; }
            size_t base = (((size_t)bb * PAD_ + py) * PAD_ + px) * 256;
            ((uint4*)(g_Ah + base))[vec] = make_uint4(0, 0, 0, 0);
        }
    }

    const int w = t >> 5, xc = t & 31;
    #pragma unroll 4
    for (int i = 0; i < 32; ++i) {
        int c = i * 8 + w;
        sm[c * 33 + xc] = x[(((size_t)b * 256 + c) * 32 + y) * 32 + xc];
    }
    __syncthreads();

    #pragma unroll 4
    for (int xi = 0; xi < 32; ++xi) {
        float v = sm[t * 33 + xi];
        g_Ah[(((size_t)b * PAD_ + y + 1) * PAD_ + xi + 1) * 256 + t] = __float2half(v);
    }
}

// ---------------------------------------------------------------------------
// Kernel 3: fp16 HMMA GEMM. CTA tile 128M x 128N, 8 warps (4M x 2N), warp
// 32x64 via m16n8k16. 36 K-chunks of 64, 3-stage cp.async ring.
// Epilogue: acc*16 + mean(bias) -> out.
// ---------------------------------------------------------------------------
#define A_ST 16384
#define B_OF 49152
#define SMEM_TOT 98304

__device__ __forceinline__ void load_chunk(uint32_t sb, int j, int ch,
                                           int b, int y0, int n0, int tid) {
    const int tap = ch >> 2;
    const int cc  = ch & 3;
    const int dy  = tap / 3, dx = tap - dy * 3;
    const int cbase = cc * 64;

    const int arow  = tid >> 1;
    const int ahalf = tid & 1;
    const uint32_t ro = (uint32_t)arow * 128 + ahalf * 64;

    const int py = y0 + (arow >> 5) + dy;
    const int px = (arow & 31) + dx;
    const char* asrc = (const char*)(g_Ah +
        (((size_t)b * PAD_ + py) * PAD_ + px) * 256 + cbase) + ahalf * 64;
    const uint32_t abase = sb + (uint32_t)j * A_ST;
    #pragma unroll
    for (int q = 0; q < 4; ++q)
        CP_ASYNC16(abase + SW128(ro + q * 16), asrc + q * 16);

    const char* bsrc = (const char*)(g_Bh +
        (size_t)(n0 + arow) * KTOT + tap * 256 + cbase) + ahalf * 64;
    const uint32_t bbase = sb + B_OF + (uint32_t)j * A_ST;
    #pragma unroll
    for (int q = 0; q < 4; ++q)
        CP_ASYNC16(bbase + SW128(ro + q * 16), bsrc + q * 16);
}

__global__ void __launch_bounds__(256, 2)
gemm_kernel(const float* __restrict__ bias, float* __restrict__ out) {
    extern __shared__ char smem[];
    const uint32_t sb = smem_u32(smem);
    const int tid  = threadIdx.x;
    const int lane = tid & 31;
    const int wid  = tid >> 5;
    const int wm   = wid & 3;
    const int wn   = wid >> 2;

    const int blk = blockIdx.x;
    const int b   = blk >> 3;
    const int y0  = (blk & 7) * 4;
    const int n0  = blockIdx.y * 128;

    float acc[2][8][4];
    #pragma unroll
    for (int mi = 0; mi < 2; ++mi)
        #pragma unroll
        for (int ni = 0; ni < 8; ++ni)
            #pragma unroll
            for (int v = 0; v < 4; ++v) acc[mi][ni][v] = 0.f;

    const uint32_t lrow = lane & 15;
    const uint32_t lcol = (lane >> 4) * 16;

    load_chunk(sb, 0, 0, b, y0, n0, tid);
    CP_COMMIT();
    load_chunk(sb, 1, 1, b, y0, n0, tid);
    CP_COMMIT();

    int stg = 0;
    for (int i = 0; i < NCH; ++i) {
        if (i + 2 < NCH) {
            load_chunk(sb, (i + 2) % 3, i + 2, b, y0, n0, tid);
            CP_COMMIT();
            CP_WAIT(2);
        } else if (i + 1 < NCH) {
            CP_WAIT(1);
        } else {
            CP_WAIT(0);
        }
        __syncthreads();

        const uint32_t abase = sb + (uint32_t)stg * A_ST;
        const uint32_t bbase = sb + B_OF + (uint32_t)stg * A_ST;

        #pragma unroll
        for (int ks = 0; ks < 4; ++ks) {
            uint32_t afr[2][4];
            #pragma unroll
            for (int mi = 0; mi < 2; ++mi) {
                uint32_t row = wm * 32 + mi * 16 + lrow;
                ldmx4(afr[mi], abase + SW128(row * 128 + ks * 32 + lcol));
            }
            uint32_t bfr[4][4];
            #pragma unroll
            for (int nq = 0; nq < 4; ++nq) {
                uint32_t row = wn * 64 + nq * 16 + lrow;
                ldmx4(bfr[nq], bbase + SW128(row * 128 + ks * 32 + lcol));
            }
            #pragma unroll
            for (int mi = 0; mi < 2; ++mi)
                #pragma unroll
                for (int ni = 0; ni < 8; ++ni)
                    mma16816(acc[mi][ni], afr[mi],
                             bfr[ni >> 1][ni & 1], bfr[ni >> 1][(ni & 1) + 2]);
        }
        __syncthreads();
        stg = (stg + 1) % 3;
    }

    // epilogue: mean bias per col, acc*16 (undo B scaling), store
    float bias2[8][2];
    #pragma unroll
    for (int ni = 0; ni < 8; ++ni) {
        const int n = n0 + wn * 64 + ni * 8 + (lane & 3) * 2;
        float s0 = 0.f, s1 = 0.f;
        #pragma unroll
        for (int s = 0; s < 9; ++s) {
            s0 += bias[s * 256 + n];
            s1 += bias[s * 256 + n + 1];
        }
        bias2[ni][0] = s0 * (1.0f / 9.0f);
        bias2[ni][1] = s1 * (1.0f / 9.0f);
    }
    #pragma unroll
    for (int mi = 0; mi < 2; ++mi) {
        const int rbase = wm * 32 + mi * 16 + (lane >> 2);
        #pragma unroll
        for (int ni = 0; ni < 8; ++ni) {
            const int n = n0 + wn * 64 + ni * 8 + (lane & 3) * 2;
            #pragma unroll
            for (int hrow = 0; hrow < 2; ++hrow) {
                const int row = rbase + hrow * 8;
                const int yy = row >> 5, xx = row & 31;
                float* op = out + (((size_t)b * N_ + n) * 32 + y0 + yy) * 32 + xx;
                op[0]   = acc[mi][ni][2 * hrow]     * 16.0f + bias2[ni][0];
                op[HW_] = acc[mi][ni][2 * hrow + 1] * 16.0f + bias2[ni][1];
            }
        }
    }
}

// ---------------------------------------------------------------------------
extern "C" void kernel_launch(void* const* d_in, const int* in_sizes, int n_in,
                              void* d_out, int out_size) {
    const float* x    = (const float*)d_in[0];
    const float* tw1  = (const float*)d_in[1];
    const float* tw2  = (const float*)d_in[2];
    const float* bias = (const float*)d_in[3];
    float* out = (float*)d_out;

    cudaFuncSetAttribute(gemm_kernel,
                         cudaFuncAttributeMaxDynamicSharedMemorySize, SMEM_TOT);

    split_pad_kernel<<<B_ * 32, 256>>>(x);
    bfly_build_kernel<<<dim3(9, 16), 256>>>(tw1, tw2);
    gemm_kernel<<<dim3(128, 2), 256, SMEM_TOT>>>(bias, out);
}

// round 13
// speedup vs baseline: 5.2566x; 1.0513x over previous
#include <cuda_runtime.h>
#include <cuda_fp16.h>
#include <cstdint>

// ---------------------------------------------------------------------------
// out = mean_s( B2_s B1_s patch_s + bias_s )  ==  3x3 conv 256->256, pad 1.
// Collapsed GEMM D[m,n] = sum_k A[m,k]*B[n,k], m=16384, n=256, k=2304.
// R13: merged prep kernel (bfly_build || split_pad run concurrently),
// single-barrier GEMM mainloop. fp16 single-pass HMMA (rel_err ~3e-4).
// ---------------------------------------------------------------------------

#define B_   16
#define C_   256
#define N_   256
#define HW_  1024
#define KTOT 2304
#define PAD_ 34
#define NCH  36

// ------------------------- device scratch (no alloc) -----------------------
__device__ __align__(16) __half g_Bh[N_ * KTOT];              // W [n][tap*256+c] * 1/144
__device__ __align__(16) __half g_Ah[B_ * PAD_ * PAD_ * C_];  // x [b][py][px][c] fp16

// ------------------------------ PTX helpers --------------------------------
__device__ __forceinline__ uint32_t smem_u32(const void* p) {
    uint32_t a;
    asm("{ .reg .u64 t; cvta.to.shared.u64 t, %1; cvt.u32.u64 %0, t; }"
        : "=r"(a) : "l"(p));
    return a;
}
#define SW128(o) ((o) ^ ((((uint32_t)(o)) >> 3) & 0x70))

#define CP_ASYNC16(dst, src) \
    asm volatile("cp.async.cg.shared.global [%0], [%1], 16;" \
                 :: "r"(dst), "l"(src) : "memory")
#define CP_COMMIT() asm volatile("cp.async.commit_group;" ::: "memory")
#define CP_WAIT(n)  asm volatile("cp.async.wait_group %0;" :: "n"(n) : "memory")

__device__ __forceinline__ void ldmx4(uint32_t* r, uint32_t addr) {
    asm volatile("ldmatrix.sync.aligned.m8n8.x4.shared.b16 {%0,%1,%2,%3}, [%4];"
                 : "=r"(r[0]), "=r"(r[1]), "=r"(r[2]), "=r"(r[3]) : "r"(addr));
}
__device__ __forceinline__ void mma16816(float* d, const uint32_t* a,
                                         uint32_t b0, uint32_t b1) {
    asm volatile(
        "mma.sync.aligned.m16n8k16.row.col.f32.f16.f16.f32 "
        "{%0,%1,%2,%3}, {%4,%5,%6,%7}, {%8,%9}, {%0,%1,%2,%3};"
        : "+f"(d[0]), "+f"(d[1]), "+f"(d[2]), "+f"(d[3])
        : "r"(a[0]), "r"(a[1]), "r"(a[2]), "r"(a[3]), "r"(b0), "r"(b1));
}

// ---------------------------------------------------------------------------
// Kernel 1 (merged prep): blocks 0..143 build butterfly weight matrices,
// blocks 144..655 transpose+convert the input (concurrent execution).
// ---------------------------------------------------------------------------
#define BFLY_BLKS 144
#define PREP_BLKS (BFLY_BLKS + 512)

__global__ void __launch_bounds__(256)
prep_kernel(const float* __restrict__ tw1, const float* __restrict__ tw2,
            const float* __restrict__ x) {
    __shared__ float sm[256 * 33];
    const int bid = blockIdx.x;
    const int tid = threadIdx.x;

    if (bid < BFLY_BLKS) {
        // ---- butterfly build: M_s = B2_s * B1_s -> fp16 * 1/144 ----
        float* M = sm;                       // pitch 17, 256*17 floats
        const int s     = bid / 16;          // tap
        const int chunk = bid & 15;          // 16-column chunk

        for (int idx = tid; idx < 256 * 16; idx += 256) {
            int n = idx >> 4, col = idx & 15;
            M[n * 17 + col] = (n == chunk * 16 + col) ? 1.0f : 0.0f;
        }

        auto stage = [&](const float* __restrict__ tw, int sh) {
            __syncthreads();
            const int st = 1 << sh;
            for (int task = tid; task < 128 * 16; task += 256) {
                int pr  = task >> 4, col = task & 15;
                int l   = pr & (st - 1);
                int k0  = ((pr >> sh) << (sh + 1)) | l;
                int k1  = k0 + st;
                const float4 t = *(const float4*)(tw + ((size_t)s * 255 + (st - 1) + l) * 4);
                float a = M[k0 * 17 + col];
                float b = M[k1 * 17 + col];
                M[k0 * 17 + col] = t.x * a + t.y * b;
                M[k1 * 17 + col] = t.z * a + t.w * b;
            }
        };

        for (int sh = 7; sh >= 0; --sh) stage(tw1, sh);   // increasing=False
        for (int sh = 0; sh <= 7; ++sh) stage(tw2, sh);   // increasing=True

        __syncthreads();
        const float sc = 1.0f / (9.0f * 16.0f);
        for (int idx = tid; idx < 256 * 16; idx += 256) {
            int col = idx & 15, n = idx >> 4;
            int c = chunk * 16 + col;
            g_Bh[(size_t)n * KTOT + s * 256 + c] = __float2half(M[n * 17 + col] * sc);
        }
    } else {
        // ---- input transpose + fp16 + border zero ----
        const int sbid = bid - BFLY_BLKS;    // 0..511
        const int b = sbid >> 5;
        const int y = sbid & 31;

        // border zero: 16 b * 132 cells * 32 uint4 = 67584 tasks over 512 blocks
        {
            int idx = sbid * 256 + tid;
            if (idx < 16 * 132 * 32) {
                int vec  = idx & 31;
                int cell = (idx >> 5) % 132;
                int bb   = idx / (132 * 32);
                int py, px;
                if (cell < 34)      { py = 0;  px = cell; }
                else if (cell < 68) { py = 33; px = cell - 34; }
                else { int r = cell - 68; py = 1 + (r >> 1); px = (r & 1) * 33; }
                size_t base = (((size_t)bb * PAD_ + py) * PAD_ + px) * 256;
                ((uint4*)(g_Ah + base))[vec] = make_uint4(0, 0, 0, 0);
            }
        }

        const int w = tid >> 5, xc = tid & 31;
        #pragma unroll 4
        for (int i = 0; i < 32; ++i) {
            int c = i * 8 + w;
            sm[c * 33 + xc] = x[(((size_t)b * 256 + c) * 32 + y) * 32 + xc];
        }
        __syncthreads();

        #pragma unroll 4
        for (int xi = 0; xi < 32; ++xi) {
            float v = sm[tid * 33 + xi];
            g_Ah[(((size_t)b * PAD_ + y + 1) * PAD_ + xi + 1) * 256 + tid] = __float2half(v);
        }
    }
}

// ---------------------------------------------------------------------------
// Kernel 2: fp16 HMMA GEMM. CTA tile 128M x 128N, 8 warps (4M x 2N), warp
// 32x64 via m16n8k16. 36 K-chunks of 64, 3-stage cp.async ring,
// single __syncthreads per iteration. Epilogue: acc*16 + mean(bias).
// ---------------------------------------------------------------------------
#define A_ST 16384
#define B_OF 49152
#define SMEM_TOT 98304

__device__ __forceinline__ void load_chunk(uint32_t sb, int j, int ch,
                                           int b, int y0, int n0, int tid) {
    const int tap = ch >> 2;
    const int cc  = ch & 3;
    const int dy  = tap / 3, dx = tap - dy * 3;
    const int cbase = cc * 64;

    const int arow  = tid >> 1;
    const int ahalf = tid & 1;
    const uint32_t ro = (uint32_t)arow * 128 + ahalf * 64;

    const int py = y0 + (arow >> 5) + dy;
    const int px = (arow & 31) + dx;
    const char* asrc = (const char*)(g_Ah +
        (((size_t)b * PAD_ + py) * PAD_ + px) * 256 + cbase) + ahalf * 64;
    const uint32_t abase = sb + (uint32_t)j * A_ST;
    #pragma unroll
    for (int q = 0; q < 4; ++q)
        CP_ASYNC16(abase + SW128(ro + q * 16), asrc + q * 16);

    const char* bsrc = (const char*)(g_Bh +
        (size_t)(n0 + arow) * KTOT + tap * 256 + cbase) + ahalf * 64;
    const uint32_t bbase = sb + B_OF + (uint32_t)j * A_ST;
    #pragma unroll
    for (int q = 0; q < 4; ++q)
        CP_ASYNC16(bbase + SW128(ro + q * 16), bsrc + q * 16);
}

__global__ void __launch_bounds__(256, 2)
gemm_kernel(const float* __restrict__ bias, float* __restrict__ out) {
    extern __shared__ char smem[];
    const uint32_t sb = smem_u32(smem);
    const int tid  = threadIdx.x;
    const int lane = tid & 31;
    const int wid  = tid >> 5;
    const int wm   = wid & 3;
    const int wn   = wid >> 2;

    const int blk = blockIdx.x;
    const int b   = blk >> 3;
    const int y0  = (blk & 7) * 4;
    const int n0  = blockIdx.y * 128;

    float acc[2][8][4];
    #pragma unroll
    for (int mi = 0; mi < 2; ++mi)
        #pragma unroll
        for (int ni = 0; ni < 8; ++ni)
            #pragma unroll
            for (int v = 0; v < 4; ++v) acc[mi][ni][v] = 0.f;

    const uint32_t lrow = lane & 15;
    const uint32_t lcol = (lane >> 4) * 16;

    load_chunk(sb, 0, 0, b, y0, n0, tid);
    CP_COMMIT();
    load_chunk(sb, 1, 1, b, y0, n0, tid);
    CP_COMMIT();

    int stg = 0;
    for (int i = 0; i < NCH; ++i) {
        if (i + 1 < NCH) { CP_WAIT(1); } else { CP_WAIT(0); }
        __syncthreads();
        // safe to refill stage (i+2)%3 == (i-1)%3: every thread's reads of it
        // (iter i-1) completed before the barrier above.
        if (i + 2 < NCH) {
            load_chunk(sb, (i + 2) % 3, i + 2, b, y0, n0, tid);
            CP_COMMIT();
        }

        const uint32_t abase = sb + (uint32_t)stg * A_ST;
        const uint32_t bbase = sb + B_OF + (uint32_t)stg * A_ST;

        #pragma unroll
        for (int ks = 0; ks < 4; ++ks) {
            uint32_t afr[2][4];
            #pragma unroll
            for (int mi = 0; mi < 2; ++mi) {
                uint32_t row = wm * 32 + mi * 16 + lrow;
                ldmx4(afr[mi], abase + SW128(row * 128 + ks * 32 + lcol));
            }
            uint32_t bfr[4][4];
            #pragma unroll
            for (int nq = 0; nq < 4; ++nq) {
                uint32_t row = wn * 64 + nq * 16 + lrow;
                ldmx4(bfr[nq], bbase + SW128(row * 128 + ks * 32 + lcol));
            }
            #pragma unroll
            for (int mi = 0; mi < 2; ++mi)
                #pragma unroll
                for (int ni = 0; ni < 8; ++ni)
                    mma16816(acc[mi][ni], afr[mi],
                             bfr[ni >> 1][ni & 1], bfr[ni >> 1][(ni & 1) + 2]);
        }
        stg = (stg + 1) % 3;
    }

    // epilogue: mean bias per col, acc*16 (undo B scaling), store
    float bias2[8][2];
    #pragma unroll
    for (int ni = 0; ni < 8; ++ni) {
        const int n = n0 + wn * 64 + ni * 8 + (lane & 3) * 2;
        float s0 = 0.f, s1 = 0.f;
        #pragma unroll
        for (int s = 0; s < 9; ++s) {
            s0 += bias[s * 256 + n];
            s1 += bias[s * 256 + n + 1];
        }
        bias2[ni][0] = s0 * (1.0f / 9.0f);
        bias2[ni][1] = s1 * (1.0f / 9.0f);
    }
    #pragma unroll
    for (int mi = 0; mi < 2; ++mi) {
        const int rbase = wm * 32 + mi * 16 + (lane >> 2);
        #pragma unroll
        for (int ni = 0; ni < 8; ++ni) {
            const int n = n0 + wn * 64 + ni * 8 + (lane & 3) * 2;
            #pragma unroll
            for (int hrow = 0; hrow < 2; ++hrow) {
                const int row = rbase + hrow * 8;
                const int yy = row >> 5, xx = row & 31;
                float* op = out + (((size_t)b * N_ + n) * 32 + y0 + yy) * 32 + xx;
                op[0]   = acc[mi][ni][2 * hrow]     * 16.0f + bias2[ni][0];
                op[HW_] = acc[mi][ni][2 * hrow + 1] * 16.0f + bias2[ni][1];
            }
        }
    }
}

// ---------------------------------------------------------------------------
extern "C" void kernel_launch(void* const* d_in, const int* in_sizes, int n_in,
                              void* d_out, int out_size) {
    const float* x    = (const float*)d_in[0];
    const float* tw1  = (const float*)d_in[1];
    const float* tw2  = (const float*)d_in[2];
    const float* bias = (const float*)d_in[3];
    float* out = (float*)d_out;

    cudaFuncSetAttribute(gemm_kernel,
                         cudaFuncAttributeMaxDynamicSharedMemorySize, SMEM_TOT);

    prep_kernel<<<PREP_BLKS, 256>>>(tw1, tw2, x);
    gemm_kernel<<<dim3(128, 2), 256, SMEM_TOT>>>(bias, out);
}